// round 14
// baseline (speedup 1.0000x reference)
#include <cuda_runtime.h>
#include <cstdint>

#define C_FEAT 64
#define NXc 432
#define NYc 496
#define S_CELLS (NXc * NYc)      // 214272 cells per batch element
#define SQ4 (S_CELLS / 4)        // float4 groups per batch/channel row (53568, % 32 == 0)
#define MAXB 8
#define TILE_Q 32                // float4-groups per block = 128 cells

// Scratch: cell -> (local pillar index + 1), 0 = empty.
// Zero-initialized at module load; gather kernel restores zeros after use.
__device__ unsigned short g_map16[MAXB * S_CELLS];

__global__ void scatter_idx_kernel(const int* __restrict__ coords, int P, int Ppb, int ncells) {
    int p = blockIdx.x * blockDim.x + threadIdx.x;
    if (p >= P) return;
    int4 c = ((const int4*)coords)[p];   // (b, z, y, x) int32
    int flat = c.x * S_CELLS + c.y + c.z * NXc + c.w;
    int local = p - c.x * Ppb;           // per-batch pillar index
    if (flat >= 0 && flat < ncells && local >= 0 && local < 0xFFFF) {
        g_map16[flat] = (unsigned short)(local + 1);
    }
}

// Block (32, 4): x = float4-group within tile, s = channel slice (16 ch each).
// Stage transposed tile (64 ch x 128 cells = 32KB) in SMEM, drain via
// cp.async.bulk shared->global (one 512B row per channel).
__global__ void __launch_bounds__(128) gather_tma_kernel(
    const float* __restrict__ feat,     // [P, 64]
    float* __restrict__ out,            // [B, 64, S_CELLS]
    int Ppb)
{
    __shared__ __align__(16) float4 tile[C_FEAT * TILE_Q];   // 32 KB

    int x = threadIdx.x;                     // 0..31
    int s = threadIdx.y;                     // 0..3
    int t = blockIdx.x * TILE_Q + x;         // global q-group (SQ4 % 32 == 0: no batch straddle)
    int b = t / SQ4;
    int q = t - b * SQ4;

    // One 8B load = 4 uint16 map entries (0 = empty, else local+1)
    uint2* mp = ((uint2*)(g_map16 + b * S_CELLS)) + q;
    uint2 mraw = *mp;

    __syncthreads();                         // all 4 slices read before slice 0 resets
    if (s == 0 && (mraw.x | mraw.y)) {
        *mp = make_uint2(0u, 0u);
    }

    unsigned m0 = mraw.x & 0xFFFFu, m1 = mraw.x >> 16;
    unsigned m2 = mraw.y & 0xFFFFu, m3 = mraw.y >> 16;

    size_t pbase = (size_t)b * (size_t)Ppb;
    const float4* f0 = (const float4*)(feat + (pbase + m0 - 1) * C_FEAT);
    const float4* f1 = (const float4*)(feat + (pbase + m1 - 1) * C_FEAT);
    const float4* f2 = (const float4*)(feat + (pbase + m2 - 1) * C_FEAT);
    const float4* f3 = (const float4*)(feat + (pbase + m3 - 1) * C_FEAT);

    const float4 z4 = make_float4(0.f, 0.f, 0.f, 0.f);

#pragma unroll
    for (int i = 0; i < 4; ++i) {
        int c4 = 4 * s + i;                  // this slice's float4-channel-group
        float4 a  = (m0 != 0u) ? f0[c4] : z4;
        float4 bb = (m1 != 0u) ? f1[c4] : z4;
        float4 cc = (m2 != 0u) ? f2[c4] : z4;
        float4 dd = (m3 != 0u) ? f3[c4] : z4;

        // 4x4 transpose into SMEM rows (one row per channel; 32 lanes -> 512B, conflict-free)
        tile[(4 * c4 + 0) * TILE_Q + x] = make_float4(a.x, bb.x, cc.x, dd.x);
        tile[(4 * c4 + 1) * TILE_Q + x] = make_float4(a.y, bb.y, cc.y, dd.y);
        tile[(4 * c4 + 2) * TILE_Q + x] = make_float4(a.z, bb.z, cc.z, dd.z);
        tile[(4 * c4 + 3) * TILE_Q + x] = make_float4(a.w, bb.w, cc.w, dd.w);
    }

    __syncthreads();                         // tile complete
    asm volatile("fence.proxy.async.shared::cta;" ::: "memory");

    int tid = x + 32 * s;                    // 0..127
    if (tid < C_FEAT) {
        // Per-block constants (same batch for whole block)
        int bb2   = (blockIdx.x * TILE_Q) / SQ4;
        int qbase = blockIdx.x * TILE_Q - bb2 * SQ4;
        float* gdst = out + ((size_t)(bb2 * C_FEAT + tid)) * S_CELLS + (size_t)qbase * 4;

        uint32_t saddr;
        asm("{ .reg .u64 t; cvta.to.shared.u64 t, %1; cvt.u32.u64 %0, t; }"
            : "=r"(saddr) : "l"(tile + tid * TILE_Q));

        asm volatile("cp.async.bulk.global.shared::cta.bulk_group [%0], [%1], %2;"
                     :: "l"(gdst), "r"(saddr), "n"(TILE_Q * 16) : "memory");
        asm volatile("cp.async.bulk.commit_group;" ::: "memory");
        asm volatile("cp.async.bulk.wait_group 0;" ::: "memory");
    }
}

extern "C" void kernel_launch(void* const* d_in, const int* in_sizes, int n_in,
                              void* d_out, int out_size) {
    const float* feat   = (const float*)d_in[0];
    const int*   coords = (const int*)d_in[1];

    int P = in_sizes[0] / C_FEAT;                 // number of pillars
    int B = out_size / (C_FEAT * S_CELLS);        // batch size from output shape
    if (B > MAXB) B = MAXB;
    int Ppb = P / B;

    int ncells = B * S_CELLS;
    scatter_idx_kernel<<<(P + 255) / 256, 256>>>(coords, P, Ppb, ncells);

    dim3 blk(32, 4);
    int nblocks = (B * SQ4) / TILE_Q;             // exact: SQ4 % 32 == 0
    gather_tma_kernel<<<nblocks, blk>>>(feat, (float*)d_out, Ppb);
}

// round 15
// speedup vs baseline: 1.0899x; 1.0899x over previous
#include <cuda_runtime.h>

#define C_FEAT 64
#define NXc 432
#define NYc 496
#define S_CELLS (NXc * NYc)      // 214272 cells per batch element
#define SQ4 (S_CELLS / 4)        // float4 groups per batch/channel row (53568, % 64 == 0)
#define MAXB 8

// Scratch: cell -> (local pillar index + 1), 0 = empty.
// Zero-initialized at module load; gather_kernel restores zeros after use,
// so the empty-map invariant holds before every kernel_launch call.
__device__ unsigned short g_map16[MAXB * S_CELLS];

__global__ void scatter_idx_kernel(const int* __restrict__ coords, int P, int Ppb, int ncells) {
    int p = blockIdx.x * blockDim.x + threadIdx.x;
    if (p >= P) return;
    int4 c = ((const int4*)coords)[p];   // (b, z, y, x) int32
    int flat = c.x * S_CELLS + c.y + c.z * NXc + c.w;
    int local = p - c.x * Ppb;           // per-batch pillar index
    if (flat >= 0 && flat < ncells && local >= 0 && local < 0xFFFF) {
        g_map16[flat] = (unsigned short)(local + 1);
    }
}

// Measured-best shape (R7): block (64, 4): x = spatial float4-group,
// y = channel slice (16 channels each). 2D grid: x covers SQ4/64, y = batch
// (removes the per-thread divide; SQ4 % 64 == 0 so no bounds checks).
__global__ void __launch_bounds__(256) gather_kernel(
    const float* __restrict__ feat,     // [P, 64]
    float4* __restrict__ out4,          // [B, 64, SQ4] float4
    int Ppb)
{
    int q = blockIdx.x * 64 + threadIdx.x;   // q-group within batch
    int b = blockIdx.y;                      // batch element
    int s = threadIdx.y;                     // channel slice 0..3

    // One 8B load = 4 uint16 map entries (0 = empty, else local+1)
    uint2* mp = ((uint2*)(g_map16 + b * S_CELLS)) + q;
    uint2 mraw = *mp;

    // All 4 slices read before slice 0 resets.
    __syncthreads();
    if (s == 0 && (mraw.x | mraw.y)) {
        *mp = make_uint2(0u, 0u);
    }

    unsigned m0 = mraw.x & 0xFFFFu, m1 = mraw.x >> 16;
    unsigned m2 = mraw.y & 0xFFFFu, m3 = mraw.y >> 16;

    size_t pbase = (size_t)b * (size_t)Ppb;
    const float4* f0 = (const float4*)(feat + (pbase + m0 - 1) * C_FEAT);
    const float4* f1 = (const float4*)(feat + (pbase + m1 - 1) * C_FEAT);
    const float4* f2 = (const float4*)(feat + (pbase + m2 - 1) * C_FEAT);
    const float4* f3 = (const float4*)(feat + (pbase + m3 - 1) * C_FEAT);

    float4* o = out4 + (size_t)b * (C_FEAT * SQ4) + q;

    const float4 z4 = make_float4(0.f, 0.f, 0.f, 0.f);

#pragma unroll
    for (int i = 0; i < 4; ++i) {
        int c4 = 4 * s + i;                 // this slice's float4-channel-group
        // plain derefs -> predicated LDG (no branches)
        float4 a  = (m0 != 0u) ? f0[c4] : z4;
        float4 bb = (m1 != 0u) ? f1[c4] : z4;
        float4 cc = (m2 != 0u) ? f2[c4] : z4;
        float4 dd = (m3 != 0u) ? f3[c4] : z4;

        // 4x4 register transpose: warp writes 32 consecutive float4 (512B) per row
        __stcs(o + (size_t)(4 * c4 + 0) * SQ4, make_float4(a.x, bb.x, cc.x, dd.x));
        __stcs(o + (size_t)(4 * c4 + 1) * SQ4, make_float4(a.y, bb.y, cc.y, dd.y));
        __stcs(o + (size_t)(4 * c4 + 2) * SQ4, make_float4(a.z, bb.z, cc.z, dd.z));
        __stcs(o + (size_t)(4 * c4 + 3) * SQ4, make_float4(a.w, bb.w, cc.w, dd.w));
    }
}

extern "C" void kernel_launch(void* const* d_in, const int* in_sizes, int n_in,
                              void* d_out, int out_size) {
    const float* feat   = (const float*)d_in[0];
    const int*   coords = (const int*)d_in[1];

    int P = in_sizes[0] / C_FEAT;                 // number of pillars
    int B = out_size / (C_FEAT * S_CELLS);        // batch size from output shape
    if (B > MAXB) B = MAXB;
    int Ppb = P / B;

    int ncells = B * S_CELLS;
    scatter_idx_kernel<<<(P + 127) / 128, 128>>>(coords, P, Ppb, ncells);

    dim3 blk(64, 4);
    dim3 grd(SQ4 / 64, B);                        // exact: SQ4 % 64 == 0
    gather_kernel<<<grd, blk>>>(feat, (float4*)d_out, Ppb);
}